// round 16
// baseline (speedup 1.0000x reference)
#include <cuda_runtime.h>
#include <cuda_bf16.h>
#include <cuda_fp16.h>
#include <math.h>
#include <cstdint>

// ---------------------------------------------------------------------------
// MLPAttention: mma.sync plain-fp16 pipeline (sm_100 base target).
// B=32, S=2048, D=1024.
// out: [0,32768) h_tilde | [32768,65536) weighted_context | [65536,131072) attn_w
// R16: score kernel feeds B fragments via direct LDG.64 from L2 (register
//      double-buffered) instead of cp.async+LDS -> removes ~55% of the
//      smem-port traffic that was pacing the tensor pipe. A stays on the
//      4-stage cp.async path (16KB stages). All other kernels = R15.
// ---------------------------------------------------------------------------

#define B_SZ   32
#define S_SZ   2048
#define D_SZ   1024
#define R_SZ   (B_SZ * S_SZ)

// Scratch (module statics: no runtime allocation)
__device__ float g_target[B_SZ * D_SZ];          // input @ W_in^T + b_c
__device__ float g_spart[2 * R_SZ];              // d-half partial scores
__device__ float g_part[B_SZ * 8 * D_SZ];        // wctx split-S partials
// Fragment-ordered fp16 planes.
// A (context): blocks [rt(512)][ks(64)][mt(8)] of [lane(32)]x16B
__device__ uint4 g_AH[(size_t)R_SZ * D_SZ / 8];  // 128MB
// B (W_c): blocks [dc(8)][ks(64)][nt(16)] of [lane(32)]x8B
__device__ uint2 g_BH[(size_t)D_SZ * D_SZ / 4];  // 2MB

// ---------------------------------------------------------------------------
// helpers
// ---------------------------------------------------------------------------
__device__ __forceinline__ uint32_t smem_u32(const void* p) {
    uint32_t a;
    asm("{ .reg .u64 t; cvta.to.shared.u64 t, %1; cvt.u32.u64 %0, t; }" : "=r"(a) : "l"(p));
    return a;
}

// pack two floats to f16x2 (lo16 = a, hi16 = b)
__device__ __forceinline__ uint32_t pk_f16x2(float a, float b) {
    uint32_t h;
    asm("cvt.rn.f16x2.f32 %0, %1, %2;" : "=r"(h) : "f"(b), "f"(a));
    return h;
}

#define MMA_F16(c, a, b)                                                        \
    asm volatile("mma.sync.aligned.m16n8k16.row.col.f32.f16.f16.f32 "           \
        "{%0,%1,%2,%3}, {%4,%5,%6,%7}, {%8,%9}, {%0,%1,%2,%3};"                 \
        : "+f"((c)[0]), "+f"((c)[1]), "+f"((c)[2]), "+f"((c)[3])                \
        : "r"((a).x), "r"((a).y), "r"((a).z), "r"((a).w),                       \
          "r"((b).x), "r"((b).y))

#define CP16(d, s)                                                              \
    asm volatile("cp.async.cg.shared.global [%0], [%1], 16;"                    \
                 :: "r"(d), "l"(s) : "memory")

// ---------------------------------------------------------------------------
// Kernel 0a: convert context to fp16 in A-fragment order (R12 version).
// ---------------------------------------------------------------------------
__global__ __launch_bounds__(256) void prep_ctx_kernel(const float* __restrict__ ctx)
{
    const int task  = blockIdx.x * 8 + (threadIdx.x >> 5);
    const int lane  = threadIdx.x & 31;
    const int mtile = task >> 6;          // 0..4095 (16-row tiles)
    const int ks    = task & 63;          // 16-wide k step

    const int  r0 = mtile * 16 + (lane >> 2);
    const int  kb = ks * 16 + (lane & 3) * 2;
    const float* p0 = ctx + (size_t)r0 * D_SZ + kb;
    const float* p1 = ctx + (size_t)(r0 + 8) * D_SZ + kb;

    float2 f00 = *(const float2*)(p0);
    float2 f10 = *(const float2*)(p1);
    float2 f02 = *(const float2*)(p0 + 8);
    float2 f12 = *(const float2*)(p1 + 8);

    uint4 h;
    h.x = pk_f16x2(f00.x, f00.y);
    h.y = pk_f16x2(f10.x, f10.y);
    h.z = pk_f16x2(f02.x, f02.y);
    h.w = pk_f16x2(f12.x, f12.y);

    const int rt = mtile >> 3, mt = mtile & 7;
    const size_t blk = ((size_t)rt * 64 + ks) * 8 + mt;
    g_AH[blk * 32 + lane] = h;
}

// ---------------------------------------------------------------------------
// Kernel 0b: convert W_c to fp16 in B-fragment order.
// ---------------------------------------------------------------------------
__global__ __launch_bounds__(256) void prep_wc_kernel(const float* __restrict__ Wc)
{
    const int task  = blockIdx.x * 8 + (threadIdx.x >> 5);
    const int lane  = threadIdx.x & 31;
    const int ntile = task >> 6;          // 0..127 (8-col tiles)
    const int ks    = task & 63;

    const int n  = ntile * 8 + (lane >> 2);
    const int kb = ks * 16 + (lane & 3) * 2;
    float2 f0 = *(const float2*)(Wc + (size_t)n * D_SZ + kb);
    float2 f2 = *(const float2*)(Wc + (size_t)n * D_SZ + kb + 8);

    uint2 h;
    h.x = pk_f16x2(f0.x, f0.y);
    h.y = pk_f16x2(f2.x, f2.y);

    const int dc = ntile >> 4, nt = ntile & 15;
    const size_t blk = ((size_t)dc * 64 + ks) * 16 + nt;
    g_BH[blk * 32 + lane] = h;
}

// ---------------------------------------------------------------------------
// Kernel 1: target[b,e] = input[b,:] @ W_in[e,:] + b_c[e]
// Single-pass batched GEMV (W_in read exactly once).  [R15]
// ---------------------------------------------------------------------------
__global__ __launch_bounds__(256) void target_kernel(
    const float* __restrict__ input,
    const float* __restrict__ W_in,
    const float* __restrict__ b_c)
{
    __shared__ float Ws[8][65];
    __shared__ float xs[32][65];
    const int tid = threadIdx.x, chunk = blockIdx.x;
    const int e = tid >> 5, b = tid & 31;

    float acc = 0.f;
    for (int k0 = 0; k0 < D_SZ; k0 += 64) {
        __syncthreads();
        {
            int idx = tid;       Ws[idx >> 6][idx & 63] =
                W_in[(size_t)(chunk * 8 + (idx >> 6)) * D_SZ + k0 + (idx & 63)];
            idx = tid + 256;     Ws[idx >> 6][idx & 63] =
                W_in[(size_t)(chunk * 8 + (idx >> 6)) * D_SZ + k0 + (idx & 63)];
        }
        #pragma unroll
        for (int j = 0; j < 8; j++) {
            int idx = j * 256 + tid, bb = idx >> 6, k = idx & 63;
            xs[bb][k] = input[bb * D_SZ + k0 + k];
        }
        __syncthreads();
        #pragma unroll
        for (int k = 0; k < 64; k++)
            acc += Ws[e][k] * xs[b][k];
    }
    const int row = chunk * 8 + e;
    g_target[b * D_SZ + row] = acc + b_c[row];
}

// ---------------------------------------------------------------------------
// Kernel 2 (dominant): mma.sync fp16 GEMM + tanh + W_v reduce -> scores.
// Grid (2 d-halves, 512 r-tiles), 256 threads (8 warps), warp grid 2m x 4n,
// warp tile 64x64. A: 4-stage x 16KB cp.async. B: direct LDG.64 from L2,
// register double-buffered one ks ahead (removes B from the smem port).
// ---------------------------------------------------------------------------
#define STAGES       4
#define A_STAGE      16384           // A only
#define TGT_OFF      (STAGES * A_STAGE)
#define WV_OFF       (TGT_OFF + 4096)
#define SC_OFF       (WV_OFF + 4096)
#define SMEM_SCORE   (SC_OFF + 2048)

__global__ __launch_bounds__(256, 1) void score_kernel(const float* __restrict__ Wv)
{
    extern __shared__ char smem[];
    const int tid   = threadIdx.x, wid = tid >> 5, lane = tid & 31;
    const int wm    = wid & 1, wn = wid >> 1;    // 2m x 4n warp grid
    const int dhalf = blockIdx.x;
    const int rt    = blockIdx.y;
    const int r0    = rt * 128, b = r0 >> 11;

    float* tgt_s = (float*)(smem + TGT_OFF);
    float* wv_s  = (float*)(smem + WV_OFF);
    float* sc_s  = (float*)(smem + SC_OFF);      // [4 wn][128 rows]
    for (int i = tid; i < D_SZ; i += 256) {
        tgt_s[i] = g_target[b * D_SZ + i];
        wv_s[i]  = Wv[i];
    }

    const uint32_t sb = smem_u32(smem);

    // A stage: k-chunk 64 (4 ks blocks), 16KB. 256 threads x 4 x 16B.
    auto issueA = [&](int it) {
        const int kc = it & 15, p = it & 3;
        const size_t aoff = ((size_t)rt * 64 + kc * 4) * 4096 + tid * 16;
        const char* sAH = (const char*)g_AH + aoff;
        const uint32_t d = sb + p * A_STAGE + tid * 16;
        #pragma unroll
        for (int r = 0; r < 4; r++)
            CP16(d + r * 4096, sAH + r * 4096);
        asm volatile("cp.async.commit_group;" ::: "memory");
    };

    // B fragment base for this warp: dc = dhalf*4 + dpair*2 + (wn>>1),
    // nt base = (wn&1)*8. frag(ks, n) at +(ks*16+n)*32 uint2.
    const int dcw_base = dhalf * 4 + (wn >> 1);
    auto ldB = [&](int it, int ks, uint2* buf) {
        const int kc = it & 15, dpair = it >> 4;
        const uint2* p = g_BH
            + (((size_t)(dcw_base + dpair * 2) * 64 + kc * 4 + ks) * 16
               + (wn & 1) * 8) * 32 + lane;
        #pragma unroll
        for (int n = 0; n < 8; n++)
            buf[n] = p[(size_t)n * 32];
    };

    issueA(0); issueA(1); issueA(2);

    uint2 bb[2][8];
    ldB(0, 0, bb[0]);

    float c[4][8][4];
    float acc[4][2];
    #pragma unroll
    for (int mi = 0; mi < 4; mi++) { acc[mi][0] = 0.f; acc[mi][1] = 0.f; }

    for (int i = 0; i < 32; i++) {
        if ((i & 15) == 0) {
            #pragma unroll
            for (int mi = 0; mi < 4; mi++)
                #pragma unroll
                for (int n = 0; n < 8; n++)
                    #pragma unroll
                    for (int q = 0; q < 4; q++) c[mi][n][q] = 0.f;
        }

        if (i <= 29)      asm volatile("cp.async.wait_group 2;" ::: "memory");
        else if (i == 30) asm volatile("cp.async.wait_group 1;" ::: "memory");
        else              asm volatile("cp.async.wait_group 0;" ::: "memory");
        __syncthreads();
        if (i + 3 < 32) issueA(i + 3);   // overlaps the MMA work below

        const char* st = smem + (i & 3) * A_STAGE;
        #pragma unroll
        for (int ks = 0; ks < 4; ks++) {
            uint2* cur = bb[ks & 1];
            uint2* nxt = bb[(ks + 1) & 1];
            // prefetch next B fragment set (covers L2 latency with MMAs below)
            if (ks < 3)          ldB(i, ks + 1, nxt);
            else if (i + 1 < 32) ldB(i + 1, 0, nxt);

            uint4 aH[4];
            #pragma unroll
            for (int mi = 0; mi < 4; mi++) {
                const int mt = wm * 4 + mi;
                aH[mi] = *(const uint4*)(st + ks * 4096 + mt * 512 + lane * 16);
            }
            #pragma unroll
            for (int mi = 0; mi < 4; mi++)
                #pragma unroll
                for (int n = 0; n < 8; n++) MMA_F16(c[mi][n], aH[mi], cur[n]);
        }

        if ((i & 15) == 15) {
            const int dpair = i >> 4;
            const int d0 = dhalf * 512 + dpair * 256 + wn * 64;
            #pragma unroll
            for (int mi = 0; mi < 4; mi++) {
                #pragma unroll
                for (int n = 0; n < 8; n++) {
                    const int col = d0 + n * 8 + (lane & 3) * 2;
                    const float w0 = wv_s[col], w1 = wv_s[col + 1];
                    const float t0 = tgt_s[col], t1 = tgt_s[col + 1];
                    acc[mi][0] += w0 * tanhf(t0 + c[mi][n][0]) + w1 * tanhf(t1 + c[mi][n][1]);
                    acc[mi][1] += w0 * tanhf(t0 + c[mi][n][2]) + w1 * tanhf(t1 + c[mi][n][3]);
                }
            }
        }
    }

    // reduce the 4 lanes sharing each output row
    #pragma unroll
    for (int mi = 0; mi < 4; mi++)
        #pragma unroll
        for (int h = 0; h < 2; h++) {
            acc[mi][h] += __shfl_xor_sync(0xffffffffu, acc[mi][h], 1);
            acc[mi][h] += __shfl_xor_sync(0xffffffffu, acc[mi][h], 2);
        }

    if ((lane & 3) == 0) {
        #pragma unroll
        for (int mi = 0; mi < 4; mi++)
            #pragma unroll
            for (int h = 0; h < 2; h++)
                sc_s[wn * 128 + wm * 64 + mi * 16 + h * 8 + (lane >> 2)] = acc[mi][h];
    }
    __syncthreads();
    if (tid < 128)
        g_spart[dhalf * R_SZ + r0 + tid] =
            (sc_s[tid] + sc_s[128 + tid]) + (sc_s[256 + tid] + sc_s[384 + tid]);
}

// ---------------------------------------------------------------------------
// Kernel 3: softmax over S per batch (sums the 2 d-half partials).
// ---------------------------------------------------------------------------
__global__ __launch_bounds__(256) void softmax_kernel(float* __restrict__ out)
{
    const int b = blockIdx.x, tid = threadIdx.x;
    __shared__ float red[256];

    float v[8];
    float mx = -1e30f;
    #pragma unroll
    for (int j = 0; j < 8; j++) {
        const int idx = b * S_SZ + j * 256 + tid;
        v[j] = g_spart[idx] + g_spart[R_SZ + idx];
        mx = fmaxf(mx, v[j]);
    }
    red[tid] = mx; __syncthreads();
    for (int s = 128; s > 0; s >>= 1) {
        if (tid < s) red[tid] = fmaxf(red[tid], red[tid + s]);
        __syncthreads();
    }
    mx = red[0];
    __syncthreads();

    float sum = 0.f;
    #pragma unroll
    for (int j = 0; j < 8; j++) { v[j] = expf(v[j] - mx); sum += v[j]; }
    red[tid] = sum; __syncthreads();
    for (int s = 128; s > 0; s >>= 1) {
        if (tid < s) red[tid] += red[tid + s];
        __syncthreads();
    }
    const float inv = 1.f / red[0];

    #pragma unroll
    for (int j = 0; j < 8; j++)
        out[65536 + b * S_SZ + j * 256 + tid] = v[j] * inv;
}

// ---------------------------------------------------------------------------
// Kernel 4a: wctx partials, split over S; 2 independent accumulation chains.
// ---------------------------------------------------------------------------
__global__ __launch_bounds__(256) void wctx_part_kernel(
    const float* __restrict__ ctx, const float* __restrict__ out)
{
    __shared__ float w_s[256];
    const int b = blockIdx.x, sc = blockIdx.y, dc = blockIdx.z, tid = threadIdx.x;
    w_s[tid] = out[65536 + b * S_SZ + sc * 256 + tid];
    __syncthreads();

    const int d = dc * 256 + tid;
    const float* C = ctx + (size_t)b * S_SZ * D_SZ + (size_t)(sc * 256) * D_SZ + d;
    float acc0 = 0.f, acc1 = 0.f;
    #pragma unroll 4
    for (int s = 0; s < 128; s++) {
        acc0 += w_s[s]       * C[(size_t)s * D_SZ];
        acc1 += w_s[s + 128] * C[(size_t)(s + 128) * D_SZ];
    }
    g_part[((b * 8 + sc) << 10) + d] = acc0 + acc1;
}

// Kernel 4b: reduce 8 partials (fixed order -> deterministic)
__global__ __launch_bounds__(256) void wctx_reduce_kernel(float* __restrict__ out)
{
    const int b = blockIdx.x, dc = blockIdx.y, tid = threadIdx.x;
    const int d = dc * 256 + tid;
    float a = 0.f;
    #pragma unroll
    for (int sc = 0; sc < 8; sc++) a += g_part[((b * 8 + sc) << 10) + d];
    out[32768 + b * D_SZ + d] = a;
}

// ---------------------------------------------------------------------------
// Kernel 5: h_tilde[b,e] = tanh( [wc, input] @ W_out[e,:] )
// Single-pass batched GEMV (W_out read exactly once).  [R15]
// ---------------------------------------------------------------------------
__global__ __launch_bounds__(256) void htilde_kernel(
    const float* __restrict__ input,
    const float* __restrict__ W_out,
    float* __restrict__ out)
{
    __shared__ float Ws[8][65];
    __shared__ float xs[32][65];
    const int tid = threadIdx.x, chunk = blockIdx.x;
    const int e = tid >> 5, b = tid & 31;

    float acc = 0.f;
    for (int k0 = 0; k0 < 2 * D_SZ; k0 += 64) {
        __syncthreads();
        {
            int idx = tid;       Ws[idx >> 6][idx & 63] =
                W_out[(size_t)(chunk * 8 + (idx >> 6)) * (2 * D_SZ) + k0 + (idx & 63)];
            idx = tid + 256;     Ws[idx >> 6][idx & 63] =
                W_out[(size_t)(chunk * 8 + (idx >> 6)) * (2 * D_SZ) + k0 + (idx & 63)];
        }
        #pragma unroll
        for (int j = 0; j < 8; j++) {
            int idx = j * 256 + tid, bb = idx >> 6, k = idx & 63;
            const int kk = k0 + k;
            xs[bb][k] = (kk < D_SZ) ? out[32768 + bb * D_SZ + kk]
                                    : input[bb * D_SZ + kk - D_SZ];
        }
        __syncthreads();
        #pragma unroll
        for (int k = 0; k < 64; k++)
            acc += Ws[e][k] * xs[b][k];
    }
    out[b * D_SZ + chunk * 8 + e] = tanhf(acc);
}

// ---------------------------------------------------------------------------
extern "C" void kernel_launch(void* const* d_in, const int* in_sizes, int n_in,
                              void* d_out, int out_size)
{
    const float* input   = (const float*)d_in[0];
    const float* context = (const float*)d_in[1];
    const float* W_in    = (const float*)d_in[2];
    const float* W_c     = (const float*)d_in[3];
    const float* b_c     = (const float*)d_in[4];
    const float* W_v     = (const float*)d_in[5];
    const float* W_out   = (const float*)d_in[6];
    float* out = (float*)d_out;

    cudaFuncSetAttribute(score_kernel,
                         cudaFuncAttributeMaxDynamicSharedMemorySize, SMEM_SCORE);

    prep_ctx_kernel  <<< 32768,          256 >>> (context);
    prep_wc_kernel   <<< 1024,           256 >>> (W_c);
    target_kernel    <<< 128,            256 >>> (input, W_in, b_c);
    score_kernel     <<< dim3(2, 512),   256, SMEM_SCORE >>> (W_v);
    softmax_kernel   <<< 32,             256 >>> (out);
    wctx_part_kernel <<< dim3(32, 8, 4), 256 >>> (context, out);
    wctx_reduce_kernel<<< dim3(32, 4),   256 >>> (out);
    htilde_kernel    <<< 128,            256 >>> (input, W_out, out);
}

// round 17
// speedup vs baseline: 1.0645x; 1.0645x over previous
#include <cuda_runtime.h>
#include <cuda_bf16.h>
#include <cuda_fp16.h>
#include <math.h>
#include <cstdint>

// ---------------------------------------------------------------------------
// MLPAttention: mma.sync plain-fp16 pipeline (sm_100 base target).
// B=32, S=2048, D=1024.
// out: [0,32768) h_tilde | [32768,65536) weighted_context | [65536,131072) attn_w
// R17: score -> 2 CTAs/SM. CTA tile 128x128 (8 warps, 4m x 2n, warp 32x64),
//      3-stage x 32KB pipeline (105KB smem), __launch_bounds__(256,2).
//      d split into QUARTERS: grid (4,512)=2048 CTAs -> 6.92 waves (98.8%).
//      16 warps resident per SM (4/SMSP) to cover LDS/epilogue gaps.
//      All other kernels = R15 (proven).
// ---------------------------------------------------------------------------

#define B_SZ   32
#define S_SZ   2048
#define D_SZ   1024
#define R_SZ   (B_SZ * S_SZ)

// Scratch (module statics: no runtime allocation)
__device__ float g_target[B_SZ * D_SZ];          // input @ W_in^T + b_c
__device__ float g_spart[4 * R_SZ];              // d-quarter partial scores
__device__ float g_part[B_SZ * 8 * D_SZ];        // wctx split-S partials
// Fragment-ordered fp16 planes.
// A (context): blocks [rt(512)][ks(64)][mt(8)] of [lane(32)]x16B
__device__ uint4 g_AH[(size_t)R_SZ * D_SZ / 8];  // 128MB
// B (W_c): blocks [dc(8)][ks(64)][nt(16)] of [lane(32)]x8B
__device__ uint2 g_BH[(size_t)D_SZ * D_SZ / 4];  // 2MB

// ---------------------------------------------------------------------------
// helpers
// ---------------------------------------------------------------------------
__device__ __forceinline__ uint32_t smem_u32(const void* p) {
    uint32_t a;
    asm("{ .reg .u64 t; cvta.to.shared.u64 t, %1; cvt.u32.u64 %0, t; }" : "=r"(a) : "l"(p));
    return a;
}

// pack two floats to f16x2 (lo16 = a, hi16 = b)
__device__ __forceinline__ uint32_t pk_f16x2(float a, float b) {
    uint32_t h;
    asm("cvt.rn.f16x2.f32 %0, %1, %2;" : "=r"(h) : "f"(b), "f"(a));
    return h;
}

#define MMA_F16(c, a, b)                                                        \
    asm volatile("mma.sync.aligned.m16n8k16.row.col.f32.f16.f16.f32 "           \
        "{%0,%1,%2,%3}, {%4,%5,%6,%7}, {%8,%9}, {%0,%1,%2,%3};"                 \
        : "+f"((c)[0]), "+f"((c)[1]), "+f"((c)[2]), "+f"((c)[3])                \
        : "r"((a).x), "r"((a).y), "r"((a).z), "r"((a).w),                       \
          "r"((b).x), "r"((b).y))

#define CP16(d, s)                                                              \
    asm volatile("cp.async.cg.shared.global [%0], [%1], 16;"                    \
                 :: "r"(d), "l"(s) : "memory")

// ---------------------------------------------------------------------------
// Kernel 0a: convert context to fp16 in A-fragment order (R12 version).
// ---------------------------------------------------------------------------
__global__ __launch_bounds__(256) void prep_ctx_kernel(const float* __restrict__ ctx)
{
    const int task  = blockIdx.x * 8 + (threadIdx.x >> 5);
    const int lane  = threadIdx.x & 31;
    const int mtile = task >> 6;          // 0..4095 (16-row tiles)
    const int ks    = task & 63;          // 16-wide k step

    const int  r0 = mtile * 16 + (lane >> 2);
    const int  kb = ks * 16 + (lane & 3) * 2;
    const float* p0 = ctx + (size_t)r0 * D_SZ + kb;
    const float* p1 = ctx + (size_t)(r0 + 8) * D_SZ + kb;

    float2 f00 = *(const float2*)(p0);
    float2 f10 = *(const float2*)(p1);
    float2 f02 = *(const float2*)(p0 + 8);
    float2 f12 = *(const float2*)(p1 + 8);

    uint4 h;
    h.x = pk_f16x2(f00.x, f00.y);
    h.y = pk_f16x2(f10.x, f10.y);
    h.z = pk_f16x2(f02.x, f02.y);
    h.w = pk_f16x2(f12.x, f12.y);

    const int rt = mtile >> 3, mt = mtile & 7;
    const size_t blk = ((size_t)rt * 64 + ks) * 8 + mt;
    g_AH[blk * 32 + lane] = h;
}

// ---------------------------------------------------------------------------
// Kernel 0b: convert W_c to fp16 in B-fragment order.
// ---------------------------------------------------------------------------
__global__ __launch_bounds__(256) void prep_wc_kernel(const float* __restrict__ Wc)
{
    const int task  = blockIdx.x * 8 + (threadIdx.x >> 5);
    const int lane  = threadIdx.x & 31;
    const int ntile = task >> 6;          // 0..127 (8-col tiles)
    const int ks    = task & 63;

    const int n  = ntile * 8 + (lane >> 2);
    const int kb = ks * 16 + (lane & 3) * 2;
    float2 f0 = *(const float2*)(Wc + (size_t)n * D_SZ + kb);
    float2 f2 = *(const float2*)(Wc + (size_t)n * D_SZ + kb + 8);

    uint2 h;
    h.x = pk_f16x2(f0.x, f0.y);
    h.y = pk_f16x2(f2.x, f2.y);

    const int dc = ntile >> 4, nt = ntile & 15;
    const size_t blk = ((size_t)dc * 64 + ks) * 16 + nt;
    g_BH[blk * 32 + lane] = h;
}

// ---------------------------------------------------------------------------
// Kernel 1: target[b,e] = input[b,:] @ W_in[e,:] + b_c[e]
// Single-pass batched GEMV (W_in read exactly once).  [R15]
// ---------------------------------------------------------------------------
__global__ __launch_bounds__(256) void target_kernel(
    const float* __restrict__ input,
    const float* __restrict__ W_in,
    const float* __restrict__ b_c)
{
    __shared__ float Ws[8][65];
    __shared__ float xs[32][65];
    const int tid = threadIdx.x, chunk = blockIdx.x;
    const int e = tid >> 5, b = tid & 31;

    float acc = 0.f;
    for (int k0 = 0; k0 < D_SZ; k0 += 64) {
        __syncthreads();
        {
            int idx = tid;       Ws[idx >> 6][idx & 63] =
                W_in[(size_t)(chunk * 8 + (idx >> 6)) * D_SZ + k0 + (idx & 63)];
            idx = tid + 256;     Ws[idx >> 6][idx & 63] =
                W_in[(size_t)(chunk * 8 + (idx >> 6)) * D_SZ + k0 + (idx & 63)];
        }
        #pragma unroll
        for (int j = 0; j < 8; j++) {
            int idx = j * 256 + tid, bb = idx >> 6, k = idx & 63;
            xs[bb][k] = input[bb * D_SZ + k0 + k];
        }
        __syncthreads();
        #pragma unroll
        for (int k = 0; k < 64; k++)
            acc += Ws[e][k] * xs[b][k];
    }
    const int row = chunk * 8 + e;
    g_target[b * D_SZ + row] = acc + b_c[row];
}

// ---------------------------------------------------------------------------
// Kernel 2 (dominant): mma.sync fp16 GEMM + tanh + W_v reduce -> scores.
// Grid (4 d-quarters, 512 r-tiles) = 2048 CTAs (6.92 waves @ 2 CTA/SM).
// 256 threads (8 warps), warp grid 4m x 2n, warp tile 32x64, CTA tile 128x128.
// 3-stage x 32KB cp.async (A 16K | B 16K); __launch_bounds__(256, 2).
// Each CTA: 2 d-chunks of 128 cols x 16 k-iters (FULL k) = 32 iterations.
// ---------------------------------------------------------------------------
#define STAGE_SC     32768           // A 16K | B 16K
#define TGT_OFF      (3 * STAGE_SC)
#define WV_OFF       (TGT_OFF + 4096)
#define SC_OFF       (WV_OFF + 4096)
#define SMEM_SCORE   (SC_OFF + 1024)

__global__ __launch_bounds__(256, 2) void score_kernel(const float* __restrict__ Wv)
{
    extern __shared__ char smem[];
    const int tid    = threadIdx.x, wid = tid >> 5, lane = tid & 31;
    const int wm     = wid & 3, wn = wid >> 2;    // 4m x 2n warp grid
    const int dquart = blockIdx.x;
    const int rt     = blockIdx.y;
    const int r0     = rt * 128, b = r0 >> 11;

    float* tgt_s = (float*)(smem + TGT_OFF);
    float* wv_s  = (float*)(smem + WV_OFF);
    float* sc_s  = (float*)(smem + SC_OFF);      // [2 wn][128 rows]
    for (int i = tid; i < D_SZ; i += 256) {
        tgt_s[i] = g_target[b * D_SZ + i];
        wv_s[i]  = Wv[i];
    }

    const uint32_t sb = smem_u32(smem);

    // one 32KB stage = k-chunk 64 (4 ks blocks) x d-chunk 128 cols.
    // it: kc = it & 15, chunk = it >> 4 (0..1), slot p = it % 3.
    auto issue = [&](int it) {
        const int kc = it & 15, dc = dquart * 2 + (it >> 4), p = it % 3;
        const size_t aoff = ((size_t)rt * 64 + kc * 4) * 4096 + tid * 16;
        const size_t boff = ((size_t)dc * 64 + kc * 4) * 4096 + tid * 16;
        const char* sAH = (const char*)g_AH + aoff;
        const char* sBH = (const char*)g_BH + boff;
        const uint32_t d = sb + p * STAGE_SC + tid * 16;
        #pragma unroll
        for (int r = 0; r < 4; r++) {
            CP16(d + r * 4096,         sAH + r * 4096);
            CP16(d + 16384 + r * 4096, sBH + r * 4096);
        }
        asm volatile("cp.async.commit_group;" ::: "memory");
    };

    issue(0); issue(1);

    float c[2][8][4];
    float acc[2][2] = {{0.f, 0.f}, {0.f, 0.f}};

    for (int i = 0; i < 32; i++) {
        if ((i & 15) == 0) {
            #pragma unroll
            for (int m = 0; m < 2; m++)
                #pragma unroll
                for (int n = 0; n < 8; n++)
                    #pragma unroll
                    for (int q = 0; q < 4; q++) c[m][n][q] = 0.f;
        }

        // stage i ready (one newer stage may stay in flight)
        if (i < 31) asm volatile("cp.async.wait_group 1;" ::: "memory");
        else        asm volatile("cp.async.wait_group 0;" ::: "memory");
        __syncthreads();
        if (i + 2 < 32) issue(i + 2);    // overlaps the MMA work below

        const char* st = smem + (i % 3) * STAGE_SC;
        #pragma unroll
        for (int ks = 0; ks < 4; ks++) {
            uint4 aH[2];
            uint2 bH[8];
            #pragma unroll
            for (int m = 0; m < 2; m++) {
                const int mt = wm * 2 + m;
                aH[m] = *(const uint4*)(st + ks * 4096 + mt * 512 + lane * 16);
            }
            #pragma unroll
            for (int n = 0; n < 8; n++) {
                const int nt = wn * 8 + n;
                bH[n] = *(const uint2*)(st + 16384 + ks * 4096 + nt * 256 + lane * 8);
            }
            #pragma unroll
            for (int m = 0; m < 2; m++)
                #pragma unroll
                for (int n = 0; n < 8; n++) MMA_F16(c[m][n], aH[m], bH[n]);
        }

        if ((i & 15) == 15) {
            const int dc = dquart * 2 + (i >> 4);
            const int d0 = dc * 128 + wn * 64;
            #pragma unroll
            for (int m = 0; m < 2; m++) {
                #pragma unroll
                for (int n = 0; n < 8; n++) {
                    const int col = d0 + n * 8 + (lane & 3) * 2;
                    const float w0 = wv_s[col], w1 = wv_s[col + 1];
                    const float t0 = tgt_s[col], t1 = tgt_s[col + 1];
                    acc[m][0] += w0 * tanhf(t0 + c[m][n][0]) + w1 * tanhf(t1 + c[m][n][1]);
                    acc[m][1] += w0 * tanhf(t0 + c[m][n][2]) + w1 * tanhf(t1 + c[m][n][3]);
                }
            }
        }
    }

    // reduce the 4 lanes sharing each output row
    #pragma unroll
    for (int m = 0; m < 2; m++)
        #pragma unroll
        for (int h = 0; h < 2; h++) {
            acc[m][h] += __shfl_xor_sync(0xffffffffu, acc[m][h], 1);
            acc[m][h] += __shfl_xor_sync(0xffffffffu, acc[m][h], 2);
        }

    // rows: wm*32 + m*16 + h*8 + (lane>>2); two wn slices then summed
    if ((lane & 3) == 0) {
        #pragma unroll
        for (int m = 0; m < 2; m++)
            #pragma unroll
            for (int h = 0; h < 2; h++)
                sc_s[wn * 128 + wm * 32 + m * 16 + h * 8 + (lane >> 2)] = acc[m][h];
    }
    __syncthreads();
    if (tid < 128)
        g_spart[dquart * R_SZ + r0 + tid] = sc_s[tid] + sc_s[128 + tid];
}

// ---------------------------------------------------------------------------
// Kernel 3: softmax over S per batch (sums the 4 d-quarter partials).
// ---------------------------------------------------------------------------
__global__ __launch_bounds__(256) void softmax_kernel(float* __restrict__ out)
{
    const int b = blockIdx.x, tid = threadIdx.x;
    __shared__ float red[256];

    float v[8];
    float mx = -1e30f;
    #pragma unroll
    for (int j = 0; j < 8; j++) {
        const int idx = b * S_SZ + j * 256 + tid;
        v[j] = (g_spart[idx] + g_spart[R_SZ + idx])
             + (g_spart[2 * R_SZ + idx] + g_spart[3 * R_SZ + idx]);
        mx = fmaxf(mx, v[j]);
    }
    red[tid] = mx; __syncthreads();
    for (int s = 128; s > 0; s >>= 1) {
        if (tid < s) red[tid] = fmaxf(red[tid], red[tid + s]);
        __syncthreads();
    }
    mx = red[0];
    __syncthreads();

    float sum = 0.f;
    #pragma unroll
    for (int j = 0; j < 8; j++) { v[j] = expf(v[j] - mx); sum += v[j]; }
    red[tid] = sum; __syncthreads();
    for (int s = 128; s > 0; s >>= 1) {
        if (tid < s) red[tid] += red[tid + s];
        __syncthreads();
    }
    const float inv = 1.f / red[0];

    #pragma unroll
    for (int j = 0; j < 8; j++)
        out[65536 + b * S_SZ + j * 256 + tid] = v[j] * inv;
}

// ---------------------------------------------------------------------------
// Kernel 4a: wctx partials, split over S; 2 independent accumulation chains.
// ---------------------------------------------------------------------------
__global__ __launch_bounds__(256) void wctx_part_kernel(
    const float* __restrict__ ctx, const float* __restrict__ out)
{
    __shared__ float w_s[256];
    const int b = blockIdx.x, sc = blockIdx.y, dc = blockIdx.z, tid = threadIdx.x;
    w_s[tid] = out[65536 + b * S_SZ + sc * 256 + tid];
    __syncthreads();

    const int d = dc * 256 + tid;
    const float* C = ctx + (size_t)b * S_SZ * D_SZ + (size_t)(sc * 256) * D_SZ + d;
    float acc0 = 0.f, acc1 = 0.f;
    #pragma unroll 4
    for (int s = 0; s < 128; s++) {
        acc0 += w_s[s]       * C[(size_t)s * D_SZ];
        acc1 += w_s[s + 128] * C[(size_t)(s + 128) * D_SZ];
    }
    g_part[((b * 8 + sc) << 10) + d] = acc0 + acc1;
}

// Kernel 4b: reduce 8 partials (fixed order -> deterministic)
__global__ __launch_bounds__(256) void wctx_reduce_kernel(float* __restrict__ out)
{
    const int b = blockIdx.x, dc = blockIdx.y, tid = threadIdx.x;
    const int d = dc * 256 + tid;
    float a = 0.f;
    #pragma unroll
    for (int sc = 0; sc < 8; sc++) a += g_part[((b * 8 + sc) << 10) + d];
    out[32768 + b * D_SZ + d] = a;
}

// ---------------------------------------------------------------------------
// Kernel 5: h_tilde[b,e] = tanh( [wc, input] @ W_out[e,:] )
// Single-pass batched GEMV (W_out read exactly once).  [R15]
// ---------------------------------------------------------------------------
__global__ __launch_bounds__(256) void htilde_kernel(
    const float* __restrict__ input,
    const float* __restrict__ W_out,
    float* __restrict__ out)
{
    __shared__ float Ws[8][65];
    __shared__ float xs[32][65];
    const int tid = threadIdx.x, chunk = blockIdx.x;
    const int e = tid >> 5, b = tid & 31;

    float acc = 0.f;
    for (int k0 = 0; k0 < 2 * D_SZ; k0 += 64) {
        __syncthreads();
        {
            int idx = tid;       Ws[idx >> 6][idx & 63] =
                W_out[(size_t)(chunk * 8 + (idx >> 6)) * (2 * D_SZ) + k0 + (idx & 63)];
            idx = tid + 256;     Ws[idx >> 6][idx & 63] =
                W_out[(size_t)(chunk * 8 + (idx >> 6)) * (2 * D_SZ) + k0 + (idx & 63)];
        }
        #pragma unroll
        for (int j = 0; j < 8; j++) {
            int idx = j * 256 + tid, bb = idx >> 6, k = idx & 63;
            const int kk = k0 + k;
            xs[bb][k] = (kk < D_SZ) ? out[32768 + bb * D_SZ + kk]
                                    : input[bb * D_SZ + kk - D_SZ];
        }
        __syncthreads();
        #pragma unroll
        for (int k = 0; k < 64; k++)
            acc += Ws[e][k] * xs[b][k];
    }
    out[b * D_SZ + chunk * 8 + e] = tanhf(acc);
}

// ---------------------------------------------------------------------------
extern "C" void kernel_launch(void* const* d_in, const int* in_sizes, int n_in,
                              void* d_out, int out_size)
{
    const float* input   = (const float*)d_in[0];
    const float* context = (const float*)d_in[1];
    const float* W_in    = (const float*)d_in[2];
    const float* W_c     = (const float*)d_in[3];
    const float* b_c     = (const float*)d_in[4];
    const float* W_v     = (const float*)d_in[5];
    const float* W_out   = (const float*)d_in[6];
    float* out = (float*)d_out;

    cudaFuncSetAttribute(score_kernel,
                         cudaFuncAttributeMaxDynamicSharedMemorySize, SMEM_SCORE);

    prep_ctx_kernel  <<< 32768,          256 >>> (context);
    prep_wc_kernel   <<< 1024,           256 >>> (W_c);
    target_kernel    <<< 128,            256 >>> (input, W_in, b_c);
    score_kernel     <<< dim3(4, 512),   256, SMEM_SCORE >>> (W_v);
    softmax_kernel   <<< 32,             256 >>> (out);
    wctx_part_kernel <<< dim3(32, 8, 4), 256 >>> (context, out);
    wctx_reduce_kernel<<< dim3(32, 4),   256 >>> (out);
    htilde_kernel    <<< 128,            256 >>> (input, W_out, out);
}